// round 10
// baseline (speedup 1.0000x reference)
#include <cuda_runtime.h>
#include <cuda_bf16.h>
#include <cstdint>

#define BB   4096      // batch rows
#define SEQ  2048      // sequence length S
#define SU   2056      // u row stride (S + E)
#define OUTW 2057      // out row stride (S + AR + 1)
#define KC   64        // chunk length
#define NCH  32        // chunks per row (SEQ / KC)
#define ORD  9         // recurrence order (AR + 1)
#define EX   8         // exogenous dim
#define BT   128       // threads per block in the two big passes
#define RPB  256       // b-rows per block (2 per thread, packed f32x2)
#define NBT  (BB / RPB)            // 16 b-tiles
#define SROW (RPB + 2)             // smem row stride (floats)
#define CV_SMEM (39 * SROW * 4)            // 40.2 KB
#define P2_SMEM ((39 + 16) * SROW * 4)     // 56.8 KB

typedef unsigned long long u64;

// Static device scratch (b-fastest layouts; 16B-aligned for LDG/STG.64)
__device__ __align__(16) float g_v[NCH * ORD * BB];   // [m][k][b]
__device__ __align__(16) float g_s[NCH * ORD * BB];   // [m][k][b]

// ---- packed f32x2 helpers -------------------------------------------------
__device__ __forceinline__ u64 pk2(float lo, float hi) {
    u64 r; asm("mov.b64 %0, {%1, %2};" : "=l"(r) : "f"(lo), "f"(hi)); return r;
}
__device__ __forceinline__ u64 f2fma(u64 a, u64 b, u64 c) {
    u64 d; asm("fma.rn.f32x2 %0, %1, %2, %3;" : "=l"(d) : "l"(a), "l"(b), "l"(c)); return d;
}
__device__ __forceinline__ u64 f2mul(u64 a, u64 b) {
    u64 d; asm("mul.rn.f32x2 %0, %1, %2;" : "=l"(d) : "l"(a), "l"(b)); return d;
}
__device__ __forceinline__ u64 f2add(u64 a, u64 b) {
    u64 d; asm("add.rn.f32x2 %0, %1, %2;" : "=l"(d) : "l"(a), "l"(b)); return d;
}

__device__ __forceinline__ void load_a(const float* __restrict__ W, float* a) {
    a[0] = -__ldg(&W[0]);
    #pragma unroll
    for (int k = 1; k < 8; k++) a[k] = __ldg(&W[k - 1]) - __ldg(&W[k]);
    a[8] = 1.0f + __ldg(&W[7]);
}

__device__ __forceinline__ void load_coefs_packed(const float* __restrict__ W,
                                                  u64* a2, u64* wu2) {
    float a[ORD];
    load_a(W, a);
    #pragma unroll
    for (int k = 0; k < ORD; k++) a2[k] = pk2(a[k], a[k]);
    #pragma unroll
    for (int e = 0; e < EX; e++) { float v = __ldg(&W[8 + e]); wu2[e] = pk2(v, v); }
}

// One packed recurrence step (2 rows). Compile-time rotation.
__device__ __forceinline__ u64 step_packed(const u64* a2, const u64* wu2,
                                           const u64* uw, const u64* w, int j) {
    u64 q0 = f2mul(wu2[0], uw[(0 + j) % 9]);
    u64 q1 = f2mul(wu2[2], uw[(2 + j) % 9]);
    u64 q2 = f2mul(wu2[4], uw[(4 + j) % 9]);
    u64 q3 = f2mul(wu2[6], uw[(6 + j) % 9]);
    q0 = f2fma(wu2[1], uw[(1 + j) % 9], q0);
    q1 = f2fma(wu2[3], uw[(3 + j) % 9], q1);
    q2 = f2fma(wu2[5], uw[(5 + j) % 9], q2);
    q3 = f2fma(wu2[7], uw[(7 + j) % 9], q3);
    u64 c = f2add(f2add(q0, q1), f2add(q2, q3));

    u64 c0 = f2fma(a2[0], w[(0 + j) % 9], c);
    u64 c1 = f2mul(a2[1], w[(1 + j) % 9]);
    u64 c2 = f2mul(a2[2], w[(2 + j) % 9]);
    u64 c3 = f2mul(a2[3], w[(3 + j) % 9]);
    c0 = f2fma(a2[4], w[(4 + j) % 9], c0);
    c1 = f2fma(a2[5], w[(5 + j) % 9], c1);
    c2 = f2fma(a2[6], w[(6 + j) % 9], c2);
    c3 = f2fma(a2[7], w[(7 + j) % 9], c3);
    u64 x = f2add(f2add(c0, c1), f2add(c2, c3));
    return f2fma(a2[8], w[(8 + j) % 9], x);      // prev-x term last: 4-cyc chain
}

// Transposed async tile load: u rows [b0, b0+255], cols [c0, c0+38] ->
// su[col][row]. cp.async 4B: GMEM side coalesced along cols of one row.
__device__ __forceinline__ void load_ut(const float* __restrict__ u,
                                        float (*su)[SROW],
                                        int b0, int m, int c0,
                                        int lane, int wr) {
    #pragma unroll 8
    for (int r = wr; r < RPB; r += 4) {
        const float* ur = u + (size_t)(b0 + r) * SU + 1 + m * KC + c0;
        unsigned int d0 = (unsigned int)__cvta_generic_to_shared(&su[lane][r]);
        asm volatile("cp.async.ca.shared.global [%0], [%1], 4;"
                     :: "r"(d0), "l"(ur + lane));
        if (lane < 7) {
            unsigned int d1 = (unsigned int)__cvta_generic_to_shared(&su[lane + 32][r]);
            asm volatile("cp.async.ca.shared.global [%0], [%1], 4;"
                         :: "r"(d1), "l"(ur + lane + 32));
        }
    }
    asm volatile("cp.async.commit_group;" ::: "memory");
}
#define CP_WAIT_ALL() asm volatile("cp.async.wait_group 0;" ::: "memory")

// ---------------------------------------------------------------------------
// Kernel 1 (cv): zero-state recurrence, 2 rows/thread packed, two 32-step
// phases. Emits final 9-window (packed) to g_v[m][k][b].
// ---------------------------------------------------------------------------
__global__ void __launch_bounds__(BT) cv_kernel(const float* __restrict__ u,
                                                const float* __restrict__ W) {
    extern __shared__ float dsm[];
    float (*su)[SROW] = (float (*)[SROW])dsm;
    int m  = blockIdx.x >> 4;
    int b0 = (blockIdx.x & 15) * RPB;
    int tid = threadIdx.x;
    int lane = tid & 31, wr = tid >> 5;
    int t2 = 2 * tid;

    load_ut(u, su, b0, m, 0, lane, wr);

    u64 a2[ORD], wu2[EX];
    load_coefs_packed(W, a2, wu2);

    CP_WAIT_ALL();
    __syncthreads();

    u64 w[ORD], uw[ORD];
    u64 z = pk2(0.0f, 0.0f);
    #pragma unroll
    for (int k = 0; k < ORD; k++) { w[k] = z; uw[k] = *(const u64*)&su[k][t2]; }

    #pragma unroll
    for (int j = 0; j < 32; j++) {
        u64 x = step_packed(a2, wu2, uw, w, j);
        if (j <= 29) uw[j % 9] = *(const u64*)&su[j + 9][t2];   // cols 9..38
        w[j % 9] = x;
    }
    __syncthreads();

    load_ut(u, su, b0, m, 32, lane, wr);    // cols 32..70 at su[c-32]
    CP_WAIT_ALL();
    __syncthreads();
    uw[30 % 9] = *(const u64*)&su[7][t2];   // col 39 (deferred refill)
    uw[31 % 9] = *(const u64*)&su[8][t2];   // col 40

    #pragma unroll
    for (int j = 32; j < KC; j++) {
        u64 x = step_packed(a2, wu2, uw, w, j);
        if (j <= 61) uw[j % 9] = *(const u64*)&su[j - 23][t2];  // col j+9
        w[j % 9] = x;
    }

    #pragma unroll
    for (int k = 0; k < ORD; k++)
        *(u64*)&g_v[((size_t)m * ORD + k) * BB + b0 + t2] = w[(k + KC) % 9];
}

// ---------------------------------------------------------------------------
// Kernel 2 (states): M = A^K in registers via lane recurrences + shfl;
// 31-step boundary chain with 2-deep v prefetch. out[b][0..8] = y.
// ---------------------------------------------------------------------------
__global__ void __launch_bounds__(32) states_kernel(const float* __restrict__ W,
                                                    const float* __restrict__ y,
                                                    float* __restrict__ out) {
    int lane = threadIdx.x;
    int b = blockIdx.x * 32 + lane;

    float a[ORD];
    load_a(W, a);

    float w[ORD];
    #pragma unroll
    for (int k = 0; k < ORD; k++) w[k] = (k == lane) ? 1.0f : 0.0f;
    #pragma unroll
    for (int p = 0; p < KC; p++) {
        float z = 0.0f;
        #pragma unroll
        for (int k = 0; k < ORD; k++) z += a[k] * w[(k + p) % 9];
        w[p % 9] = z;
    }
    float MT[ORD * ORD];
    #pragma unroll
    for (int r = 0; r < ORD; r++)
        #pragma unroll
        for (int k = 0; k < ORD; k++)
            MT[r * ORD + k] = __shfl_sync(0xffffffffu, w[(k + KC) % 9], r);

    float s[ORD];
    #pragma unroll
    for (int k = 0; k < ORD; k++) {
        s[k] = y[(size_t)b * ORD + k];
        out[(size_t)b * OUTW + k] = s[k];
        g_s[(size_t)k * BB + b] = s[k];
    }

    float va[ORD], vb[ORD];
    #pragma unroll
    for (int k = 0; k < ORD; k++) va[k] = g_v[(size_t)k * BB + b];
    #pragma unroll
    for (int k = 0; k < ORD; k++) vb[k] = g_v[((size_t)ORD + k) * BB + b];

    #pragma unroll
    for (int m = 0; m < NCH - 1; m++) {
        float ns[ORD];
        #pragma unroll
        for (int k = 0; k < ORD; k++) ns[k] = va[k];
        #pragma unroll
        for (int k = 0; k < ORD; k++) va[k] = vb[k];
        if (m + 2 <= NCH - 2) {
            const float* gv = g_v + ((size_t)(m + 2) * ORD) * BB + b;
            #pragma unroll
            for (int k = 0; k < ORD; k++) vb[k] = gv[(size_t)k * BB];
        }
        #pragma unroll
        for (int r = 0; r < ORD; r++) {
            float sr = s[r];
            #pragma unroll
            for (int k = 0; k < ORD; k++) ns[k] += MT[r * ORD + k] * sr;
        }
        float* gs = g_s + ((size_t)(m + 1) * ORD) * BB + b;
        #pragma unroll
        for (int k = 0; k < ORD; k++) { s[k] = ns[k]; gs[(size_t)k * BB] = s[k]; }
    }
}

// ---------------------------------------------------------------------------
// Kernel 3 (pass2): true-state replay, packed 2 rows/thread; stages 16 steps
// in smem (STS.64) and flushes to out in coalesced 64B row segments.
// ---------------------------------------------------------------------------
__global__ void __launch_bounds__(BT) pass2_kernel(const float* __restrict__ u,
                                                   const float* __restrict__ W,
                                                   float* __restrict__ out) {
    extern __shared__ float dsm[];
    float (*su)[SROW] = (float (*)[SROW])dsm;
    float (*sb)[SROW] = (float (*)[SROW])(dsm + 39 * SROW);
    int m  = blockIdx.x >> 4;
    int b0 = (blockIdx.x & 15) * RPB;
    int tid = threadIdx.x;
    int lane = tid & 31, wr = tid >> 5;
    int t2 = 2 * tid;
    int ocol0 = ORD + m * KC;

    load_ut(u, su, b0, m, 0, lane, wr);

    u64 a2[ORD], wu2[EX];
    load_coefs_packed(W, a2, wu2);

    u64 w[ORD], uw[ORD];
    #pragma unroll
    for (int k = 0; k < ORD; k++)
        w[k] = *(const u64*)&g_s[((size_t)m * ORD + k) * BB + b0 + t2];

    CP_WAIT_ALL();
    __syncthreads();
    #pragma unroll
    for (int k = 0; k < ORD; k++) uw[k] = *(const u64*)&su[k][t2];

    #pragma unroll
    for (int j = 0; j < 32; j++) {
        u64 x = step_packed(a2, wu2, uw, w, j);
        if (j <= 29) uw[j % 9] = *(const u64*)&su[j + 9][t2];
        w[j % 9] = x;
        *(u64*)&sb[j & 15][t2] = x;
        if ((j & 15) == 15) {
            __syncthreads();
            int jj = j & ~15;
            #pragma unroll
            for (int q = 0; q < 32; q++) {
                int e  = q * BT + tid;
                int tp = e & 15;
                int bp = e >> 4;
                out[(size_t)(b0 + bp) * OUTW + ocol0 + jj + tp] = sb[tp][bp];
            }
            __syncthreads();
        }
    }

    load_ut(u, su, b0, m, 32, lane, wr);
    CP_WAIT_ALL();
    __syncthreads();
    uw[30 % 9] = *(const u64*)&su[7][t2];   // col 39
    uw[31 % 9] = *(const u64*)&su[8][t2];   // col 40

    #pragma unroll
    for (int j = 32; j < KC; j++) {
        u64 x = step_packed(a2, wu2, uw, w, j);
        if (j <= 61) uw[j % 9] = *(const u64*)&su[j - 23][t2];
        w[j % 9] = x;
        *(u64*)&sb[j & 15][t2] = x;
        if ((j & 15) == 15) {
            __syncthreads();
            int jj = j & ~15;
            #pragma unroll
            for (int q = 0; q < 32; q++) {
                int e  = q * BT + tid;
                int tp = e & 15;
                int bp = e >> 4;
                out[(size_t)(b0 + bp) * OUTW + ocol0 + jj + tp] = sb[tp][bp];
            }
            __syncthreads();
        }
    }
}

// ---------------------------------------------------------------------------
extern "C" void kernel_launch(void* const* d_in, const int* in_sizes, int n_in,
                              void* d_out, int out_size) {
    const float* y = (const float*)d_in[0];
    const float* u = (const float*)d_in[1];
    const float* W = (const float*)d_in[2];
    for (int i = 0; i < n_in; i++) {
        if (in_sizes[i] == BB * ORD)      y = (const float*)d_in[i];
        else if (in_sizes[i] == BB * SU)  u = (const float*)d_in[i];
        else if (in_sizes[i] == 16)       W = (const float*)d_in[i];
    }
    float* out = (float*)d_out;

    cudaFuncSetAttribute(cv_kernel,    cudaFuncAttributeMaxDynamicSharedMemorySize, CV_SMEM);
    cudaFuncSetAttribute(pass2_kernel, cudaFuncAttributeMaxDynamicSharedMemorySize, P2_SMEM);

    cv_kernel<<<NCH * NBT, BT, CV_SMEM>>>(u, W);       // 512 x 128
    states_kernel<<<BB / 32, 32>>>(W, y, out);         // 128 x 32
    pass2_kernel<<<NCH * NBT, BT, P2_SMEM>>>(u, W, out);
}

// round 11
// speedup vs baseline: 1.1420x; 1.1420x over previous
#include <cuda_runtime.h>
#include <cuda_bf16.h>
#include <cstdint>

#define BB   4096      // batch rows
#define SEQ  2048      // sequence length S
#define SU   2056      // u row stride (S + E)
#define OUTW 2057      // out row stride (S + AR + 1)
#define KC   64        // chunk length
#define NCH  32        // chunks per row (SEQ / KC)
#define ORD  9         // recurrence order (AR + 1)
#define EX   8         // exogenous dim
#define BT   128       // threads per block in the two big passes

// Static device scratch (b-fastest layouts, coalesced for lane = b)
__device__ float g_v[NCH * ORD * BB];      // [m][k][b] zero-state final windows
__device__ float g_s[NCH * ORD * BB];      // [m][k][b] true boundary states
__device__ float g_x[SEQ * BB];            // [t][b] zero-state outputs

__device__ __forceinline__ void load_a(const float* __restrict__ W, float* a) {
    a[0] = -__ldg(&W[0]);
    #pragma unroll
    for (int k = 1; k < 8; k++) a[k] = __ldg(&W[k - 1]) - __ldg(&W[k]);
    a[8] = 1.0f + __ldg(&W[7]);
}

// Full recurrence step (c from u window + state terms), compile-time rotation.
__device__ __forceinline__ float step_rec(const float* a, const float* wu,
                                          const float* uw, const float* w, int j) {
    float e0 = wu[0] * uw[(0 + j) % 9] + wu[1] * uw[(1 + j) % 9];
    float e1 = wu[2] * uw[(2 + j) % 9] + wu[3] * uw[(3 + j) % 9];
    float e2 = wu[4] * uw[(4 + j) % 9] + wu[5] * uw[(5 + j) % 9];
    float e3 = wu[6] * uw[(6 + j) % 9] + wu[7] * uw[(7 + j) % 9];
    float c  = (e0 + e1) + (e2 + e3);
    float s0 = c + a[0] * w[(0 + j) % 9];
    float s1 = a[1] * w[(1 + j) % 9] + a[2] * w[(2 + j) % 9];
    float s2 = a[3] * w[(3 + j) % 9] + a[4] * w[(4 + j) % 9];
    float s3 = a[5] * w[(5 + j) % 9] + a[6] * w[(6 + j) % 9];
    float x  = ((s0 + s1) + (s2 + s3)) + a[7] * w[(7 + j) % 9];
    return fmaf(a[8], w[(8 + j) % 9], x);
}

// Homogeneous step (no input term): 9 FMA-class ops.
__device__ __forceinline__ float step_hom(const float* a, const float* w, int j) {
    float s0 = a[0] * w[(0 + j) % 9] + a[1] * w[(1 + j) % 9];
    float s1 = a[2] * w[(2 + j) % 9] + a[3] * w[(3 + j) % 9];
    float s2 = a[4] * w[(4 + j) % 9] + a[5] * w[(5 + j) % 9];
    float s3 = a[6] * w[(6 + j) % 9] + a[7] * w[(7 + j) % 9];
    float d  = (s0 + s1) + (s2 + s3);
    return fmaf(a[8], w[(8 + j) % 9], d);
}

// Cooperative phased tile load: cols [c0, c0+38] of 128 u-rows into su.
__device__ __forceinline__ void load_utile(const float* __restrict__ u,
                                           float su[BT][41],
                                           int b0, int m, int c0,
                                           int lane, int wr) {
    #pragma unroll
    for (int r = wr; r < BT; r += 4) {
        const float* ur = u + (size_t)(b0 + r) * SU + 1 + m * KC + c0;
        su[r][lane] = ur[lane];
        if (lane < 7) su[r][lane + 32] = ur[lane + 32];
    }
}

// ---------------------------------------------------------------------------
// Kernel 1 (cv): zero-state recurrence per (chunk m, row b), two 32-step
// phases (21 KB smem). Streams x_zero to g_x[t][b] (coalesced) and emits
// the final 9-window to g_v[m][k][b].
// ---------------------------------------------------------------------------
__global__ void __launch_bounds__(BT) cv_kernel(const float* __restrict__ u,
                                                const float* __restrict__ W) {
    __shared__ float su[BT][41];           // stride 41: gcd(41,32)=1, conflict-free
    int m  = blockIdx.x >> 5;
    int b0 = (blockIdx.x & 31) * BT;
    int tid = threadIdx.x;
    int lane = tid & 31, wr = tid >> 5;

    float a[ORD], wu[EX];
    load_a(W, a);
    #pragma unroll
    for (int e = 0; e < EX; e++) wu[e] = __ldg(&W[8 + e]);

    load_utile(u, su, b0, m, 0, lane, wr);
    __syncthreads();

    float* gx = g_x + (size_t)(m * KC) * BB + b0 + tid;

    float w[ORD], uw[ORD];
    #pragma unroll
    for (int k = 0; k < ORD; k++) { w[k] = 0.0f; uw[k] = su[tid][k]; }

    #pragma unroll
    for (int j = 0; j < 32; j++) {
        float x = step_rec(a, wu, uw, w, j);
        if (j <= 29) uw[j % 9] = su[tid][j + 9];   // cols 9..38
        w[j % 9] = x;
        gx[(size_t)j * BB] = x;
    }
    __syncthreads();

    load_utile(u, su, b0, m, 32, lane, wr);        // cols 32..70 at su[.][c-32]
    __syncthreads();
    uw[30 % 9] = su[tid][7];   // col 39 (deferred refill of step 30)
    uw[31 % 9] = su[tid][8];   // col 40 (deferred refill of step 31)

    #pragma unroll
    for (int j = 32; j < KC; j++) {
        float x = step_rec(a, wu, uw, w, j);
        if (j <= 61) uw[j % 9] = su[tid][j - 23];  // col j+9
        w[j % 9] = x;
        gx[(size_t)j * BB] = x;
    }

    float* gv = g_v + ((size_t)m * ORD) * BB + b0 + tid;
    #pragma unroll
    for (int k = 0; k < ORD; k++) gv[(size_t)k * BB] = w[(k + KC) % 9];
}

// ---------------------------------------------------------------------------
// Kernel 2 (states): M = A^K in registers via lane recurrences + shfl;
// 31-step boundary chain with 2-deep v prefetch. out[b][0..8] = y.
// ---------------------------------------------------------------------------
__global__ void __launch_bounds__(32) states_kernel(const float* __restrict__ W,
                                                    const float* __restrict__ y,
                                                    float* __restrict__ out) {
    int lane = threadIdx.x;
    int b = blockIdx.x * 32 + lane;

    float a[ORD];
    load_a(W, a);

    float w[ORD];
    #pragma unroll
    for (int k = 0; k < ORD; k++) w[k] = (k == lane) ? 1.0f : 0.0f;
    #pragma unroll
    for (int p = 0; p < KC; p++) {
        float z = 0.0f;
        #pragma unroll
        for (int k = 0; k < ORD; k++) z += a[k] * w[(k + p) % 9];
        w[p % 9] = z;
    }
    float MT[ORD * ORD];
    #pragma unroll
    for (int r = 0; r < ORD; r++)
        #pragma unroll
        for (int k = 0; k < ORD; k++)
            MT[r * ORD + k] = __shfl_sync(0xffffffffu, w[(k + KC) % 9], r);

    float s[ORD];
    #pragma unroll
    for (int k = 0; k < ORD; k++) {
        s[k] = y[(size_t)b * ORD + k];
        out[(size_t)b * OUTW + k] = s[k];
        g_s[(size_t)k * BB + b] = s[k];
    }

    float va[ORD], vb[ORD];
    #pragma unroll
    for (int k = 0; k < ORD; k++) va[k] = g_v[(size_t)k * BB + b];
    #pragma unroll
    for (int k = 0; k < ORD; k++) vb[k] = g_v[((size_t)ORD + k) * BB + b];

    #pragma unroll
    for (int m = 0; m < NCH - 1; m++) {
        float ns[ORD];
        #pragma unroll
        for (int k = 0; k < ORD; k++) ns[k] = va[k];
        #pragma unroll
        for (int k = 0; k < ORD; k++) va[k] = vb[k];
        if (m + 2 <= NCH - 2) {
            const float* gv = g_v + ((size_t)(m + 2) * ORD) * BB + b;
            #pragma unroll
            for (int k = 0; k < ORD; k++) vb[k] = gv[(size_t)k * BB];
        }
        #pragma unroll
        for (int r = 0; r < ORD; r++) {
            float sr = s[r];
            #pragma unroll
            for (int k = 0; k < ORD; k++) ns[k] += MT[r * ORD + k] * sr;
        }
        float* gs = g_s + ((size_t)(m + 1) * ORD) * BB + b;
        #pragma unroll
        for (int k = 0; k < ORD; k++) { s[k] = ns[k]; gs[(size_t)k * BB] = s[k]; }
    }
}

// ---------------------------------------------------------------------------
// Kernel 3 (pass2): out = x_zero + d, where d follows the HOMOGENEOUS
// recurrence seeded by the true boundary state s (linearity). No u tile,
// no phases: 9 FMA + 1 coalesced LDG + 1 STS per step; 16-step smem staging
// then coalesced 64B out-row flush. Low smem (8 KB) + low regs -> high occ.
// ---------------------------------------------------------------------------
__global__ void __launch_bounds__(BT) pass2_kernel(const float* __restrict__ W,
                                                   float* __restrict__ out) {
    __shared__ float sb[16][BT + 1];
    int m  = blockIdx.x >> 5;
    int b0 = (blockIdx.x & 31) * BT;
    int tid = threadIdx.x;
    int ocol0 = ORD + m * KC;

    float a[ORD];
    load_a(W, a);

    float w[ORD];
    const float* gs = g_s + ((size_t)m * ORD) * BB + b0 + tid;
    #pragma unroll
    for (int k = 0; k < ORD; k++) w[k] = gs[(size_t)k * BB];

    const float* gx = g_x + (size_t)(m * KC) * BB + b0 + tid;

    #pragma unroll
    for (int j = 0; j < KC; j++) {
        float d = step_hom(a, w, j);
        w[j % 9] = d;
        sb[j & 15][tid] = d + gx[(size_t)j * BB];
        if ((j & 15) == 15) {
            __syncthreads();
            int jj = j & ~15;
            #pragma unroll
            for (int q = 0; q < 16; q++) {
                int e  = q * BT + tid;
                int tp = e & 15;
                int bp = e >> 4;
                out[(size_t)(b0 + bp) * OUTW + ocol0 + jj + tp] = sb[tp][bp];
            }
            __syncthreads();
        }
    }
}

// ---------------------------------------------------------------------------
extern "C" void kernel_launch(void* const* d_in, const int* in_sizes, int n_in,
                              void* d_out, int out_size) {
    const float* y = (const float*)d_in[0];
    const float* u = (const float*)d_in[1];
    const float* W = (const float*)d_in[2];
    for (int i = 0; i < n_in; i++) {
        if (in_sizes[i] == BB * ORD)      y = (const float*)d_in[i];
        else if (in_sizes[i] == BB * SU)  u = (const float*)d_in[i];
        else if (in_sizes[i] == 16)       W = (const float*)d_in[i];
    }
    float* out = (float*)d_out;

    cv_kernel<<<NCH * (BB / BT), BT>>>(u, W);       // 1024 x 128
    states_kernel<<<BB / 32, 32>>>(W, y, out);      // 128 x 32
    pass2_kernel<<<NCH * (BB / BT), BT>>>(W, out);  // 1024 x 128
}

// round 12
// speedup vs baseline: 1.1530x; 1.0097x over previous
#include <cuda_runtime.h>
#include <cuda_bf16.h>
#include <cstdint>

#define BB   4096      // batch rows
#define SEQ  2048      // sequence length S
#define SU   2056      // u row stride (S + E)
#define OUTW 2057      // out row stride (S + AR + 1)
#define KC   64        // chunk length
#define NCH  32        // chunks per row (SEQ / KC)
#define ORD  9         // recurrence order (AR + 1)
#define EX   8         // exogenous dim
#define BT   128       // threads per block in the two big passes

// Static device scratch (b-fastest layouts, coalesced for lane = b)
__device__ float g_v[NCH * ORD * BB];      // [m][k][b] zero-state final windows
__device__ float g_s[NCH * ORD * BB];      // [m][k][b] true boundary states
__device__ float g_x[SEQ * BB];            // [t][b] zero-state outputs

__device__ __forceinline__ void load_a(const float* __restrict__ W, float* a) {
    a[0] = -__ldg(&W[0]);
    #pragma unroll
    for (int k = 1; k < 8; k++) a[k] = __ldg(&W[k - 1]) - __ldg(&W[k]);
    a[8] = 1.0f + __ldg(&W[7]);
}

// Full recurrence step (c from u window + state terms), compile-time rotation.
__device__ __forceinline__ float step_rec(const float* a, const float* wu,
                                          const float* uw, const float* w, int j) {
    float e0 = wu[0] * uw[(0 + j) % 9] + wu[1] * uw[(1 + j) % 9];
    float e1 = wu[2] * uw[(2 + j) % 9] + wu[3] * uw[(3 + j) % 9];
    float e2 = wu[4] * uw[(4 + j) % 9] + wu[5] * uw[(5 + j) % 9];
    float e3 = wu[6] * uw[(6 + j) % 9] + wu[7] * uw[(7 + j) % 9];
    float c  = (e0 + e1) + (e2 + e3);
    float s0 = c + a[0] * w[(0 + j) % 9];
    float s1 = a[1] * w[(1 + j) % 9] + a[2] * w[(2 + j) % 9];
    float s2 = a[3] * w[(3 + j) % 9] + a[4] * w[(4 + j) % 9];
    float s3 = a[5] * w[(5 + j) % 9] + a[6] * w[(6 + j) % 9];
    float x  = ((s0 + s1) + (s2 + s3)) + a[7] * w[(7 + j) % 9];
    return fmaf(a[8], w[(8 + j) % 9], x);
}

// Homogeneous step (no input term): 9 FMA-class ops.
__device__ __forceinline__ float step_hom(const float* a, const float* w, int j) {
    float s0 = a[0] * w[(0 + j) % 9] + a[1] * w[(1 + j) % 9];
    float s1 = a[2] * w[(2 + j) % 9] + a[3] * w[(3 + j) % 9];
    float s2 = a[4] * w[(4 + j) % 9] + a[5] * w[(5 + j) % 9];
    float s3 = a[6] * w[(6 + j) % 9] + a[7] * w[(7 + j) % 9];
    float d  = (s0 + s1) + (s2 + s3);
    return fmaf(a[8], w[(8 + j) % 9], d);
}

__device__ __forceinline__ void cpa4(void* smem, const void* gmem) {
    unsigned int d = (unsigned int)__cvta_generic_to_shared(smem);
    asm volatile("cp.async.ca.shared.global [%0], [%1], 4;" :: "r"(d), "l"(gmem));
}

// Cooperative phased tile load: cols [c0, c0+38] of 128 u-rows into su.
__device__ __forceinline__ void load_utile(const float* __restrict__ u,
                                           float su[BT][41],
                                           int b0, int m, int c0,
                                           int lane, int wr) {
    #pragma unroll
    for (int r = wr; r < BT; r += 4) {
        const float* ur = u + (size_t)(b0 + r) * SU + 1 + m * KC + c0;
        su[r][lane] = ur[lane];
        if (lane < 7) su[r][lane + 32] = ur[lane + 32];
    }
}

// ---------------------------------------------------------------------------
// Kernel 1 (cv): zero-state recurrence per (chunk m, row b), two 32-step
// phases (21 KB smem). Streams x_zero to g_x[t][b] (coalesced) and emits
// the final 9-window to g_v[m][k][b].
// ---------------------------------------------------------------------------
__global__ void __launch_bounds__(BT) cv_kernel(const float* __restrict__ u,
                                                const float* __restrict__ W) {
    __shared__ float su[BT][41];           // stride 41: gcd(41,32)=1, conflict-free
    int m  = blockIdx.x >> 5;
    int b0 = (blockIdx.x & 31) * BT;
    int tid = threadIdx.x;
    int lane = tid & 31, wr = tid >> 5;

    float a[ORD], wu[EX];
    load_a(W, a);
    #pragma unroll
    for (int e = 0; e < EX; e++) wu[e] = __ldg(&W[8 + e]);

    load_utile(u, su, b0, m, 0, lane, wr);
    __syncthreads();

    float* gx = g_x + (size_t)(m * KC) * BB + b0 + tid;

    float w[ORD], uw[ORD];
    #pragma unroll
    for (int k = 0; k < ORD; k++) { w[k] = 0.0f; uw[k] = su[tid][k]; }

    #pragma unroll
    for (int j = 0; j < 32; j++) {
        float x = step_rec(a, wu, uw, w, j);
        if (j <= 29) uw[j % 9] = su[tid][j + 9];   // cols 9..38
        w[j % 9] = x;
        gx[(size_t)j * BB] = x;
    }
    __syncthreads();

    load_utile(u, su, b0, m, 32, lane, wr);        // cols 32..70 at su[.][c-32]
    __syncthreads();
    uw[30 % 9] = su[tid][7];   // col 39 (deferred refill of step 30)
    uw[31 % 9] = su[tid][8];   // col 40 (deferred refill of step 31)

    #pragma unroll
    for (int j = 32; j < KC; j++) {
        float x = step_rec(a, wu, uw, w, j);
        if (j <= 61) uw[j % 9] = su[tid][j - 23];  // col j+9
        w[j % 9] = x;
        gx[(size_t)j * BB] = x;
    }

    float* gv = g_v + ((size_t)m * ORD) * BB + b0 + tid;
    #pragma unroll
    for (int k = 0; k < ORD; k++) gv[(size_t)k * BB] = w[(k + KC) % 9];
}

// ---------------------------------------------------------------------------
// Kernel 2 (states): M = A^K in registers via lane recurrences + shfl;
// 31-step boundary chain with 2-deep v prefetch. out[b][0..8] = y.
// ---------------------------------------------------------------------------
__global__ void __launch_bounds__(32) states_kernel(const float* __restrict__ W,
                                                    const float* __restrict__ y,
                                                    float* __restrict__ out) {
    int lane = threadIdx.x;
    int b = blockIdx.x * 32 + lane;

    float a[ORD];
    load_a(W, a);

    float w[ORD];
    #pragma unroll
    for (int k = 0; k < ORD; k++) w[k] = (k == lane) ? 1.0f : 0.0f;
    #pragma unroll
    for (int p = 0; p < KC; p++) {
        float z = 0.0f;
        #pragma unroll
        for (int k = 0; k < ORD; k++) z += a[k] * w[(k + p) % 9];
        w[p % 9] = z;
    }
    float MT[ORD * ORD];
    #pragma unroll
    for (int r = 0; r < ORD; r++)
        #pragma unroll
        for (int k = 0; k < ORD; k++)
            MT[r * ORD + k] = __shfl_sync(0xffffffffu, w[(k + KC) % 9], r);

    float s[ORD];
    #pragma unroll
    for (int k = 0; k < ORD; k++) {
        s[k] = y[(size_t)b * ORD + k];
        out[(size_t)b * OUTW + k] = s[k];
        g_s[(size_t)k * BB + b] = s[k];
    }

    float va[ORD], vb[ORD];
    #pragma unroll
    for (int k = 0; k < ORD; k++) va[k] = g_v[(size_t)k * BB + b];
    #pragma unroll
    for (int k = 0; k < ORD; k++) vb[k] = g_v[((size_t)ORD + k) * BB + b];

    #pragma unroll
    for (int m = 0; m < NCH - 1; m++) {
        float ns[ORD];
        #pragma unroll
        for (int k = 0; k < ORD; k++) ns[k] = va[k];
        #pragma unroll
        for (int k = 0; k < ORD; k++) va[k] = vb[k];
        if (m + 2 <= NCH - 2) {
            const float* gv = g_v + ((size_t)(m + 2) * ORD) * BB + b;
            #pragma unroll
            for (int k = 0; k < ORD; k++) vb[k] = gv[(size_t)k * BB];
        }
        #pragma unroll
        for (int r = 0; r < ORD; r++) {
            float sr = s[r];
            #pragma unroll
            for (int k = 0; k < ORD; k++) ns[k] += MT[r * ORD + k] * sr;
        }
        float* gs = g_s + ((size_t)(m + 1) * ORD) * BB + b;
        #pragma unroll
        for (int k = 0; k < ORD; k++) { s[k] = ns[k]; gs[(size_t)k * BB] = s[k]; }
    }
}

// ---------------------------------------------------------------------------
// Kernel 3 (pass2): out = x_zero + d (homogeneous chain from true boundary
// state). x_zero arrives via double-buffered cp.async groups (16 steps x 128b
// = 8 KB each), one group in flight while the previous computes/flushes.
// Flush fuses the add during the smem transpose write.
// ---------------------------------------------------------------------------
__global__ void __launch_bounds__(BT) pass2_kernel(const float* __restrict__ W,
                                                   float* __restrict__ out) {
    __shared__ float sgx[2][16][BT + 1];
    __shared__ float sb[16][BT + 1];
    int m  = blockIdx.x >> 5;
    int b0 = (blockIdx.x & 31) * BT;
    int tid = threadIdx.x;
    int ocol0 = ORD + m * KC;

    const float* gx = g_x + (size_t)(m * KC) * BB + b0 + tid;

    // Prologue: group 0 in flight while we load coefs and the boundary state
    #pragma unroll
    for (int j = 0; j < 16; j++)
        cpa4(&sgx[0][j][tid], gx + (size_t)j * BB);
    asm volatile("cp.async.commit_group;" ::: "memory");

    float a[ORD];
    load_a(W, a);

    float w[ORD];
    const float* gs = g_s + ((size_t)m * ORD) * BB + b0 + tid;
    #pragma unroll
    for (int k = 0; k < ORD; k++) w[k] = gs[(size_t)k * BB];

    #pragma unroll
    for (int g = 0; g < 4; g++) {
        if (g < 3) {
            #pragma unroll
            for (int j = 0; j < 16; j++)
                cpa4(&sgx[(g + 1) & 1][j][tid], gx + (size_t)((g + 1) * 16 + j) * BB);
            asm volatile("cp.async.commit_group;" ::: "memory");
            asm volatile("cp.async.wait_group 1;" ::: "memory");   // group g done
        } else {
            asm volatile("cp.async.wait_group 0;" ::: "memory");
        }
        __syncthreads();

        #pragma unroll
        for (int jj = 0; jj < 16; jj++) {
            int j = g * 16 + jj;
            float d = step_hom(a, w, j);
            w[j % 9] = d;
            sb[jj][tid] = d;
        }
        __syncthreads();

        #pragma unroll
        for (int q = 0; q < 16; q++) {
            int e  = q * BT + tid;
            int tp = e & 15;
            int bp = e >> 4;
            out[(size_t)(b0 + bp) * OUTW + ocol0 + g * 16 + tp]
                = sb[tp][bp] + sgx[g & 1][tp][bp];
        }
        __syncthreads();   // sb + sgx[(g+1)&1] must be free before next round
    }
}

// ---------------------------------------------------------------------------
extern "C" void kernel_launch(void* const* d_in, const int* in_sizes, int n_in,
                              void* d_out, int out_size) {
    const float* y = (const float*)d_in[0];
    const float* u = (const float*)d_in[1];
    const float* W = (const float*)d_in[2];
    for (int i = 0; i < n_in; i++) {
        if (in_sizes[i] == BB * ORD)      y = (const float*)d_in[i];
        else if (in_sizes[i] == BB * SU)  u = (const float*)d_in[i];
        else if (in_sizes[i] == 16)       W = (const float*)d_in[i];
    }
    float* out = (float*)d_out;

    cv_kernel<<<NCH * (BB / BT), BT>>>(u, W);       // 1024 x 128
    states_kernel<<<BB / 32, 32>>>(W, y, out);      // 128 x 32
    pass2_kernel<<<NCH * (BB / BT), BT>>>(W, out);  // 1024 x 128
}